// round 8
// baseline (speedup 1.0000x reference)
#include <cuda_runtime.h>
#include <cstdint>

// x: (B=8, C=512, T=16, W=28, H=28) fp32, contiguous.
// All three branches decompose onto 4x4x4 = 64 window maxes m4[tt][wi][hi]
// (window 4x7x7, stride 4x7x7); temporal multiply is identity (L=1):
//   out[0]      = max over all 64                      (n=1)
//   out[1+tt2]  = mean_{wi2,hi2} max over 2x2x2 block  (n=2)
//   out[3+tt]   = mean_{wi,hi}   m4[tt][wi][hi]        (n=4)
// Grid: 1024 blocks x 4 consecutive slices each  -> single wave on 148 SMs.

#define SLICE   12544   // 16*28*28
#define TCHUNK  3136    // 4*28*28 (one temporal window-depth)
#define SPB     4       // slices per block
#define NBLK    1024    // 4096 / SPB

__device__ __forceinline__ void cp_async16(uint32_t dst_smem, const void* src) {
    asm volatile("cp.async.cg.shared.global [%0], [%1], 16;\n"
                 :: "r"(dst_smem), "l"(src));
}
__device__ __forceinline__ void cp_commit() {
    asm volatile("cp.async.commit_group;\n" ::: "memory");
}
template <int N>
__device__ __forceinline__ void cp_wait() {
    asm volatile("cp.async.wait_group %0;\n" :: "n"(N) : "memory");
}

__global__ __launch_bounds__(256, 8)
void tmp3d_fused_kernel(const float* __restrict__ x, float* __restrict__ out) {
    __shared__ float tile[2][TCHUNK];   // double buffer: 2 x 12.5 KB
    __shared__ float pm[4][112];        // per-half-row partial maxes [hi][t'*28+w]
    __shared__ float m4s[64];           // [tt*16 + wi*4 + hi] (per current slice)

    const int tid = threadIdx.x;
    // 4 consecutive slices = 16 contiguous t-chunks
    const float* base = x + blockIdx.x * (SPB * SLICE);   // max offset < 2^26 floats

    const uint32_t tile_s = (uint32_t)__cvta_generic_to_shared(&tile[0][0]);

    // ---- prefetch: global chunk g (0..15) -> buffer g&1 (784 x 16B LDGSTS) ----
    auto prefetch = [&](int g) {
        const float* src = base + g * TCHUNK;
        const uint32_t dst = tile_s + (g & 1) * (TCHUNK * 4);
        cp_async16(dst + tid * 16, src + tid * 4);
        cp_async16(dst + (tid + 256) * 16, src + (tid + 256) * 4);
        cp_async16(dst + (tid + 512) * 16, src + (tid + 512) * 4);
        if (tid < 784 - 768)
            cp_async16(dst + (tid + 768) * 16, src + (tid + 768) * 4);
        cp_commit();
    };

    prefetch(0);
    prefetch(1);

    #pragma unroll 1
    for (int s = 0; s < SPB; s++) {
        #pragma unroll
        for (int tc = 0; tc < 4; tc++) {
            const int g = s * 4 + tc;
            // entering chunk g, groups 0..g+1 committed; wait_group 1 => g landed
            if (g == 15) cp_wait<0>(); else cp_wait<1>();
            __syncthreads();

            const float* buf = tile[g & 1];

            // ---- row phase: 224 threads, one half-row (14 floats) each ----
            // half 0 -> hi{0,1}, half 1 -> hi{2,3}. Conflict-free LDS.128.
            if (tid < 224) {
                const int half = tid / 112;          // 0 or 1
                const int r    = tid - half * 112;   // row index (t'*28 + w)
                const float4* rp =
                    reinterpret_cast<const float4*>(buf + r * 28 + half * 12);
                float4 v0 = rp[0], v1 = rp[1], v2 = rp[2], v3 = rp[3];
                float ma, mb;
                if (half == 0) {
                    ma = fmaxf(fmaxf(fmaxf(v0.x, v0.y), fmaxf(v0.z, v0.w)),
                               fmaxf(fmaxf(v1.x, v1.y), v1.z));
                    mb = fmaxf(fmaxf(fmaxf(v1.w, v2.x), fmaxf(v2.y, v2.z)),
                               fmaxf(fmaxf(v2.w, v3.x), v3.y));
                } else {
                    ma = fmaxf(fmaxf(fmaxf(v0.z, v0.w), fmaxf(v1.x, v1.y)),
                               fmaxf(fmaxf(v1.z, v1.w), v2.x));
                    mb = fmaxf(fmaxf(fmaxf(v2.y, v2.z), fmaxf(v2.w, v3.x)),
                               fmaxf(fmaxf(v3.y, v3.z), v3.w));
                }
                pm[2 * half + 0][r] = ma;
                pm[2 * half + 1][r] = mb;
            }
            __syncthreads();   // pm ready AND all tile[g&1] reads done

            // ---- keep the DMA stream rolling: prefetch chunk g+2 ----
            if (g < 14) prefetch(g + 2);

            // ---- window phase: 16 windows of this chunk, threads 0..15 ----
            if (tid < 16) {
                const int wi = tid >> 2;
                const int hi = tid & 3;
                const float* p = &pm[hi][wi * 7];
                float m = -3.402823466e+38f;
                #pragma unroll
                for (int t = 0; t < 4; t++) {
                    #pragma unroll
                    for (int dw = 0; dw < 7; dw++)
                        m = fmaxf(m, p[t * 28 + dw]);
                }
                m4s[tc * 16 + wi * 4 + hi] = m;
            }
        }
        __syncthreads();   // m4s complete; also orders window pm-reads vs next row

        // ---- finishing tree for slice s: 7 outputs ----
        if (tid < 7) {
            float r;
            if (tid == 0) {
                float m = m4s[0];
                #pragma unroll
                for (int i = 1; i < 64; i++) m = fmaxf(m, m4s[i]);
                r = m;
            } else if (tid < 3) {
                const int tt2 = tid - 1;
                float acc = 0.0f;
                #pragma unroll
                for (int wi2 = 0; wi2 < 2; wi2++) {
                    #pragma unroll
                    for (int hi2 = 0; hi2 < 2; hi2++) {
                        float m = -3.402823466e+38f;
                        #pragma unroll
                        for (int dt = 0; dt < 2; dt++)
                            #pragma unroll
                            for (int dw = 0; dw < 2; dw++)
                                #pragma unroll
                                for (int dh = 0; dh < 2; dh++)
                                    m = fmaxf(m, m4s[(2*tt2 + dt) * 16 +
                                                     (2*wi2 + dw) * 4 + (2*hi2 + dh)]);
                        acc += m;
                    }
                }
                r = acc * 0.25f;
            } else {
                const int tt = tid - 3;
                float acc = 0.0f;
                #pragma unroll
                for (int i = 0; i < 16; i++) acc += m4s[tt * 16 + i];
                r = acc * (1.0f / 16.0f);
            }
            out[(blockIdx.x * SPB + s) * 7 + tid] = r;
        }
        // tree reads of m4s are ordered before next slice's window writes by
        // the top-of-loop __syncthreads (wait + sync) of chunk (s+1, 0).
    }
}

extern "C" void kernel_launch(void* const* d_in, const int* in_sizes, int n_in,
                              void* d_out, int out_size) {
    const float* x = (const float*)d_in[0];
    float* out = (float*)d_out;
    tmp3d_fused_kernel<<<NBLK, 256>>>(x, out);
}

// round 10
// speedup vs baseline: 1.1440x; 1.1440x over previous
#include <cuda_runtime.h>
#include <cstdint>

// x: (B=8, C=512, T=16, W=28, H=28) fp32, contiguous.
// All three branches decompose onto 4x4x4 = 64 window maxes m4[tt][wi][hi]
// (window 4x7x7, stride 4x7x7); temporal multiply is identity (L=1):
//   out[0]      = max over all 64                      (n=1)
//   out[1+tt2]  = mean_{wi2,hi2} max over 2x2x2 block  (n=2)
//   out[3+tt]   = mean_{wi,hi}   m4[tt][wi][hi]        (n=4)
// R8 post-mortem: 1 slice/block + many schedulable blocks wins; this round
// deepens the cp.async pipeline to 3 buffers (2-group wait margin).

#define SLICE   12544   // 16*28*28
#define TCHUNK  3136    // 4*28*28 (one temporal window-depth)
#define NBC     4096    // 8*512

__device__ __forceinline__ void cp_async16(uint32_t dst_smem, const void* src) {
    asm volatile("cp.async.cg.shared.global [%0], [%1], 16;\n"
                 :: "r"(dst_smem), "l"(src));
}
__device__ __forceinline__ void cp_commit() {
    asm volatile("cp.async.commit_group;\n" ::: "memory");
}
template <int N>
__device__ __forceinline__ void cp_wait() {
    asm volatile("cp.async.wait_group %0;\n" :: "n"(N) : "memory");
}

__global__ __launch_bounds__(256, 5)
void tmp3d_fused_kernel(const float* __restrict__ x, float* __restrict__ out) {
    __shared__ float tile[3][TCHUNK];   // triple buffer: 3 x 12.5 KB
    __shared__ float pm[4][112];        // per-half-row partial maxes [hi][t'*28+w]
    __shared__ float m4s[64];           // [tt*16 + wi*4 + hi]

    const int bc  = blockIdx.x;
    const int tid = threadIdx.x;
    const float* slice = x + bc * SLICE;

    const uint32_t tile_s = (uint32_t)__cvta_generic_to_shared(&tile[0][0]);

    // ---- prefetch: chunk c -> buffer c%3 (784 x 16B LDGSTS) ----
    auto prefetch = [&](int c, int b) {
        const float* src = slice + c * TCHUNK;
        const uint32_t dst = tile_s + b * (TCHUNK * 4);
        cp_async16(dst + tid * 16, src + tid * 4);
        cp_async16(dst + (tid + 256) * 16, src + (tid + 256) * 4);
        cp_async16(dst + (tid + 512) * 16, src + (tid + 512) * 4);
        if (tid < 784 - 768)
            cp_async16(dst + (tid + 768) * 16, src + (tid + 768) * 4);
        cp_commit();
    };

    prefetch(0, 0);
    prefetch(1, 1);
    prefetch(2, 2);

    #pragma unroll
    for (int tc = 0; tc < 4; tc++) {
        // groups committed at this point: tc=0 -> {0,1,2}; tc>=1 -> {0..3}.
        // wait so that group tc has landed:
        if (tc <= 1)      cp_wait<2>();
        else if (tc == 2) cp_wait<1>();
        else              cp_wait<0>();
        __syncthreads();

        const float* buf = tile[tc % 3];

        // ---- row phase: 224 threads, one half-row (14 floats) each ----
        // half 0 -> hi{0,1}, half 1 -> hi{2,3}. Conflict-free LDS.128.
        if (tid < 224) {
            const int half = tid / 112;          // 0 or 1
            const int r    = tid - half * 112;   // row index (t'*28 + w)
            const float4* rp =
                reinterpret_cast<const float4*>(buf + r * 28 + half * 12);
            float4 v0 = rp[0], v1 = rp[1], v2 = rp[2], v3 = rp[3];
            float ma, mb;
            if (half == 0) {
                ma = fmaxf(fmaxf(fmaxf(v0.x, v0.y), fmaxf(v0.z, v0.w)),
                           fmaxf(fmaxf(v1.x, v1.y), v1.z));
                mb = fmaxf(fmaxf(fmaxf(v1.w, v2.x), fmaxf(v2.y, v2.z)),
                           fmaxf(fmaxf(v2.w, v3.x), v3.y));
            } else {
                ma = fmaxf(fmaxf(fmaxf(v0.z, v0.w), fmaxf(v1.x, v1.y)),
                           fmaxf(fmaxf(v1.z, v1.w), v2.x));
                mb = fmaxf(fmaxf(fmaxf(v2.y, v2.z), fmaxf(v2.w, v3.x)),
                           fmaxf(fmaxf(v3.y, v3.z), v3.w));
            }
            pm[2 * half + 0][r] = ma;
            pm[2 * half + 1][r] = mb;
        }
        __syncthreads();   // pm ready AND all tile[tc%3] reads done

        // ---- buffer tc%3 now free: prefetch chunk 3 (iter 0 only) ----
        if (tc == 0) prefetch(3, 0);

        // ---- window phase: 16 windows of this chunk, threads 0..15 ----
        if (tid < 16) {
            const int wi = tid >> 2;
            const int hi = tid & 3;
            const float* p = &pm[hi][wi * 7];
            float m = -3.402823466e+38f;
            #pragma unroll
            for (int t = 0; t < 4; t++) {
                #pragma unroll
                for (int dw = 0; dw < 7; dw++)
                    m = fmaxf(m, p[t * 28 + dw]);
            }
            m4s[tc * 16 + wi * 4 + hi] = m;
        }
        // next iteration's top __syncthreads orders window pm-reads
        // before the next row phase overwrites pm.
    }
    __syncthreads();   // m4s complete

    // ---- finishing tree: 7 outputs ----
    if (tid < 7) {
        float r;
        if (tid == 0) {
            float m = m4s[0];
            #pragma unroll
            for (int i = 1; i < 64; i++) m = fmaxf(m, m4s[i]);
            r = m;
        } else if (tid < 3) {
            const int tt2 = tid - 1;
            float acc = 0.0f;
            #pragma unroll
            for (int wi2 = 0; wi2 < 2; wi2++) {
                #pragma unroll
                for (int hi2 = 0; hi2 < 2; hi2++) {
                    float m = -3.402823466e+38f;
                    #pragma unroll
                    for (int dt = 0; dt < 2; dt++)
                        #pragma unroll
                        for (int dw = 0; dw < 2; dw++)
                            #pragma unroll
                            for (int dh = 0; dh < 2; dh++)
                                m = fmaxf(m, m4s[(2*tt2 + dt) * 16 +
                                                 (2*wi2 + dw) * 4 + (2*hi2 + dh)]);
                    acc += m;
                }
            }
            r = acc * 0.25f;
        } else {
            const int tt = tid - 3;
            float acc = 0.0f;
            #pragma unroll
            for (int i = 0; i < 16; i++) acc += m4s[tt * 16 + i];
            r = acc * (1.0f / 16.0f);
        }
        out[bc * 7 + tid] = r;
    }
}

extern "C" void kernel_launch(void* const* d_in, const int* in_sizes, int n_in,
                              void* d_out, int out_size) {
    const float* x = (const float*)d_in[0];
    float* out = (float*)d_out;
    tmp3d_fused_kernel<<<NBC, 256>>>(x, out);
}

// round 11
// speedup vs baseline: 1.1502x; 1.0054x over previous
#include <cuda_runtime.h>
#include <cstdint>

// x: (B=8, C=512, T=16, W=28, H=28) fp32, contiguous.
// All three branches decompose onto 4x4x4 = 64 window maxes m4[tt][wi][hi]
// (window 4x7x7, stride 4x7x7); temporal multiply is identity (L=1):
//   out[0]      = max over all 64                      (n=1)
//   out[1+tt2]  = mean_{wi2,hi2} max over 2x2x2 block  (n=2)
//   out[3+tt]   = mean_{wi,hi}   m4[tt][wi][hi]        (n=4)
// R10 post-mortem: pipeline depth is not binding; plateau is wave packing.
// This round: R7 double-buffer design, but buffers padded so static smem
// = 30 KB -> 7 blocks/SM -> 4096/1036 = 3.95 waves (last wave 92% full)
// instead of 8 blocks/SM -> 3.46 waves (last wave 46% full).

#define SLICE     12544   // 16*28*28
#define TCHUNK    3136    // 4*28*28 (one temporal window-depth)
#define BUFPAD    448     // pad floats per buffer (occupancy shaping)
#define BUFSTRIDE (TCHUNK + BUFPAD)
#define NBC       4096    // 8*512

__device__ __forceinline__ void cp_async16(uint32_t dst_smem, const void* src) {
    asm volatile("cp.async.cg.shared.global [%0], [%1], 16;\n"
                 :: "r"(dst_smem), "l"(src));
}
__device__ __forceinline__ void cp_commit() {
    asm volatile("cp.async.commit_group;\n" ::: "memory");
}
template <int N>
__device__ __forceinline__ void cp_wait() {
    asm volatile("cp.async.wait_group %0;\n" :: "n"(N) : "memory");
}

__global__ __launch_bounds__(256, 7)
void tmp3d_fused_kernel(const float* __restrict__ x, float* __restrict__ out) {
    __shared__ float tile[2 * BUFSTRIDE];   // 2 padded buffers: 28 KB
    __shared__ float pm[4][112];            // per-half-row partials [hi][t'*28+w]
    __shared__ float m4s[64];               // [tt*16 + wi*4 + hi]

    const int bc  = blockIdx.x;
    const int tid = threadIdx.x;
    const float* slice = x + bc * SLICE;

    const uint32_t tile_s = (uint32_t)__cvta_generic_to_shared(&tile[0]);

    // ---- prefetch: chunk c -> buffer b (784 x 16B LDGSTS) ----
    auto prefetch = [&](int c, int b) {
        const float* src = slice + c * TCHUNK;
        const uint32_t dst = tile_s + b * (BUFSTRIDE * 4);
        cp_async16(dst + tid * 16, src + tid * 4);
        cp_async16(dst + (tid + 256) * 16, src + (tid + 256) * 4);
        cp_async16(dst + (tid + 512) * 16, src + (tid + 512) * 4);
        if (tid < 784 - 768)
            cp_async16(dst + (tid + 768) * 16, src + (tid + 768) * 4);
        cp_commit();
    };

    prefetch(0, 0);
    prefetch(1, 1);

    #pragma unroll
    for (int tc = 0; tc < 4; tc++) {
        // entering chunk tc, groups 0..tc+1 committed; wait_group 1 => tc landed
        if (tc == 3) cp_wait<0>(); else cp_wait<1>();
        __syncthreads();

        const float* buf = tile + (tc & 1) * BUFSTRIDE;

        // ---- row phase: 224 threads, one half-row (14 floats) each ----
        // half 0 -> hi{0,1}, half 1 -> hi{2,3}. Conflict-free LDS.128.
        if (tid < 224) {
            const int half = tid / 112;          // 0 or 1
            const int r    = tid - half * 112;   // row index (t'*28 + w)
            const float4* rp =
                reinterpret_cast<const float4*>(buf + r * 28 + half * 12);
            float4 v0 = rp[0], v1 = rp[1], v2 = rp[2], v3 = rp[3];
            float ma, mb;
            if (half == 0) {
                ma = fmaxf(fmaxf(fmaxf(v0.x, v0.y), fmaxf(v0.z, v0.w)),
                           fmaxf(fmaxf(v1.x, v1.y), v1.z));
                mb = fmaxf(fmaxf(fmaxf(v1.w, v2.x), fmaxf(v2.y, v2.z)),
                           fmaxf(fmaxf(v2.w, v3.x), v3.y));
            } else {
                ma = fmaxf(fmaxf(fmaxf(v0.z, v0.w), fmaxf(v1.x, v1.y)),
                           fmaxf(fmaxf(v1.z, v1.w), v2.x));
                mb = fmaxf(fmaxf(fmaxf(v2.y, v2.z), fmaxf(v2.w, v3.x)),
                           fmaxf(fmaxf(v3.y, v3.z), v3.w));
            }
            pm[2 * half + 0][r] = ma;
            pm[2 * half + 1][r] = mb;
        }
        __syncthreads();   // pm ready AND all buffer reads done

        // ---- keep the DMA stream rolling: prefetch chunk tc+2 ----
        if (tc < 2) prefetch(tc + 2, tc & 1);

        // ---- window phase: 16 windows of this chunk, threads 0..15 ----
        if (tid < 16) {
            const int wi = tid >> 2;
            const int hi = tid & 3;
            const float* p = &pm[hi][wi * 7];
            float m = -3.402823466e+38f;
            #pragma unroll
            for (int t = 0; t < 4; t++) {
                #pragma unroll
                for (int dw = 0; dw < 7; dw++)
                    m = fmaxf(m, p[t * 28 + dw]);
            }
            m4s[tc * 16 + wi * 4 + hi] = m;
        }
        // next iteration's top __syncthreads orders window pm-reads
        // before the next row phase overwrites pm.
    }
    __syncthreads();   // m4s complete

    // ---- finishing tree: 7 outputs ----
    if (tid < 7) {
        float r;
        if (tid == 0) {
            float m = m4s[0];
            #pragma unroll
            for (int i = 1; i < 64; i++) m = fmaxf(m, m4s[i]);
            r = m;
        } else if (tid < 3) {
            const int tt2 = tid - 1;
            float acc = 0.0f;
            #pragma unroll
            for (int wi2 = 0; wi2 < 2; wi2++) {
                #pragma unroll
                for (int hi2 = 0; hi2 < 2; hi2++) {
                    float m = -3.402823466e+38f;
                    #pragma unroll
                    for (int dt = 0; dt < 2; dt++)
                        #pragma unroll
                        for (int dw = 0; dw < 2; dw++)
                            #pragma unroll
                            for (int dh = 0; dh < 2; dh++)
                                m = fmaxf(m, m4s[(2*tt2 + dt) * 16 +
                                                 (2*wi2 + dw) * 4 + (2*hi2 + dh)]);
                    acc += m;
                }
            }
            r = acc * 0.25f;
        } else {
            const int tt = tid - 3;
            float acc = 0.0f;
            #pragma unroll
            for (int i = 0; i < 16; i++) acc += m4s[tt * 16 + i];
            r = acc * (1.0f / 16.0f);
        }
        out[bc * 7 + tid] = r;
    }
}

extern "C" void kernel_launch(void* const* d_in, const int* in_sizes, int n_in,
                              void* d_out, int out_size) {
    const float* x = (const float*)d_in[0];
    float* out = (float*)d_out;
    tmp3d_fused_kernel<<<NBC, 256>>>(x, out);
}

// round 12
// speedup vs baseline: 1.1534x; 1.0027x over previous
#include <cuda_runtime.h>
#include <cstdint>

// x: (B=8, C=512, T=16, W=28, H=28) fp32, contiguous.
// All three branches decompose onto 4x4x4 = 64 window maxes m4[tt][wi][hi]
// (window 4x7x7, stride 4x7x7); temporal multiply is identity (L=1):
//   out[0]      = max over all 64                      (n=1)
//   out[1+tt2]  = mean_{wi2,hi2} max over 2x2x2 block  (n=2)
//   out[3+tt]   = mean_{wi,hi}   m4[tt][wi][hi]        (n=4)
// R11 + software-pipelined window phase: pm double-buffered; window(tc-1)
// runs on warp 7 (idle during row phase) concurrently with row(tc).
// Smem sized ~29.3 KB -> exactly 7 blocks/SM (best wave packing: 3.95 waves).

#define SLICE     12544   // 16*28*28
#define TCHUNK    3136    // 4*28*28 (one temporal window-depth)
#define BUFPAD    128     // pad floats per buffer (occupancy shaping)
#define BUFSTRIDE (TCHUNK + BUFPAD)
#define NBC       4096    // 8*512

__device__ __forceinline__ void cp_async16(uint32_t dst_smem, const void* src) {
    asm volatile("cp.async.cg.shared.global [%0], [%1], 16;\n"
                 :: "r"(dst_smem), "l"(src));
}
__device__ __forceinline__ void cp_commit() {
    asm volatile("cp.async.commit_group;\n" ::: "memory");
}
template <int N>
__device__ __forceinline__ void cp_wait() {
    asm volatile("cp.async.wait_group %0;\n" :: "n"(N) : "memory");
}

__global__ __launch_bounds__(256, 7)
void tmp3d_fused_kernel(const float* __restrict__ x, float* __restrict__ out) {
    __shared__ float tile[2 * BUFSTRIDE];   // 2 padded buffers: ~25.5 KB
    __shared__ float pm[2][4][112];         // double-buffered partials [buf][hi][row]
    __shared__ float m4s[64];               // [tt*16 + wi*4 + hi]

    const int bc  = blockIdx.x;
    const int tid = threadIdx.x;
    const float* slice = x + bc * SLICE;

    const uint32_t tile_s = (uint32_t)__cvta_generic_to_shared(&tile[0]);

    // ---- prefetch: chunk c -> buffer b (784 x 16B LDGSTS) ----
    auto prefetch = [&](int c, int b) {
        const float* src = slice + c * TCHUNK;
        const uint32_t dst = tile_s + b * (BUFSTRIDE * 4);
        cp_async16(dst + tid * 16, src + tid * 4);
        cp_async16(dst + (tid + 256) * 16, src + (tid + 256) * 4);
        cp_async16(dst + (tid + 512) * 16, src + (tid + 512) * 4);
        if (tid < 784 - 768)
            cp_async16(dst + (tid + 768) * 16, src + (tid + 768) * 4);
        cp_commit();
    };

    // ---- window reduce for chunk tcw, executed by 16 threads (lane16 = tid%16 mapping) ----
    auto window16 = [&](int tcw, int w16) {
        const int wi = w16 >> 2;
        const int hi = w16 & 3;
        const float* p = &pm[tcw & 1][hi][wi * 7];
        float m = -3.402823466e+38f;
        #pragma unroll
        for (int t = 0; t < 4; t++) {
            #pragma unroll
            for (int dw = 0; dw < 7; dw++)
                m = fmaxf(m, p[t * 28 + dw]);
        }
        m4s[tcw * 16 + wi * 4 + hi] = m;
    };

    prefetch(0, 0);
    prefetch(1, 1);

    #pragma unroll
    for (int tc = 0; tc < 4; tc++) {
        // entering chunk tc, groups 0..tc+1 committed; wait_group 1 => tc landed
        if (tc == 3) cp_wait<0>(); else cp_wait<1>();
        __syncthreads();

        const float* buf = tile + (tc & 1) * BUFSTRIDE;

        if (tid < 224) {
            // ---- row phase (warps 0-6): one half-row (14 floats) each ----
            // half 0 -> hi{0,1}, half 1 -> hi{2,3}. Conflict-free LDS.128.
            const int half = tid / 112;          // 0 or 1
            const int r    = tid - half * 112;   // row index (t'*28 + w)
            const float4* rp =
                reinterpret_cast<const float4*>(buf + r * 28 + half * 12);
            float4 v0 = rp[0], v1 = rp[1], v2 = rp[2], v3 = rp[3];
            float ma, mb;
            if (half == 0) {
                ma = fmaxf(fmaxf(fmaxf(v0.x, v0.y), fmaxf(v0.z, v0.w)),
                           fmaxf(fmaxf(v1.x, v1.y), v1.z));
                mb = fmaxf(fmaxf(fmaxf(v1.w, v2.x), fmaxf(v2.y, v2.z)),
                           fmaxf(fmaxf(v2.w, v3.x), v3.y));
            } else {
                ma = fmaxf(fmaxf(fmaxf(v0.z, v0.w), fmaxf(v1.x, v1.y)),
                           fmaxf(fmaxf(v1.z, v1.w), v2.x));
                mb = fmaxf(fmaxf(fmaxf(v2.y, v2.z), fmaxf(v2.w, v3.x)),
                           fmaxf(fmaxf(v3.y, v3.z), v3.w));
            }
            pm[tc & 1][2 * half + 0][r] = ma;
            pm[tc & 1][2 * half + 1][r] = mb;
        } else if (tc > 0 && tid < 240) {
            // ---- pipelined window phase (warp 7): chunk tc-1 ----
            window16(tc - 1, tid - 224);
        }
        __syncthreads();   // pm[tc&1] ready AND all buffer reads done

        // ---- keep the DMA stream rolling: prefetch chunk tc+2 ----
        if (tc < 2) prefetch(tc + 2, tc & 1);
    }

    // ---- final window phase: chunk 3 ----
    if (tid < 16) window16(3, tid);
    __syncthreads();   // m4s complete

    // ---- finishing tree: 7 outputs ----
    if (tid < 7) {
        float r;
        if (tid == 0) {
            float m = m4s[0];
            #pragma unroll
            for (int i = 1; i < 64; i++) m = fmaxf(m, m4s[i]);
            r = m;
        } else if (tid < 3) {
            const int tt2 = tid - 1;
            float acc = 0.0f;
            #pragma unroll
            for (int wi2 = 0; wi2 < 2; wi2++) {
                #pragma unroll
                for (int hi2 = 0; hi2 < 2; hi2++) {
                    float m = -3.402823466e+38f;
                    #pragma unroll
                    for (int dt = 0; dt < 2; dt++)
                        #pragma unroll
                        for (int dw = 0; dw < 2; dw++)
                            #pragma unroll
                            for (int dh = 0; dh < 2; dh++)
                                m = fmaxf(m, m4s[(2*tt2 + dt) * 16 +
                                                 (2*wi2 + dw) * 4 + (2*hi2 + dh)]);
                    acc += m;
                }
            }
            r = acc * 0.25f;
        } else {
            const int tt = tid - 3;
            float acc = 0.0f;
            #pragma unroll
            for (int i = 0; i < 16; i++) acc += m4s[tt * 16 + i];
            r = acc * (1.0f / 16.0f);
        }
        out[bc * 7 + tid] = r;
    }
}

extern "C" void kernel_launch(void* const* d_in, const int* in_sizes, int n_in,
                              void* d_out, int out_size) {
    const float* x = (const float*)d_in[0];
    float* out = (float*)d_out;
    tmp3d_fused_kernel<<<NBC, 256>>>(x, out);
}